// round 1
// baseline (speedup 1.0000x reference)
#include <cuda_runtime.h>
#include <cstddef>

#define NB    512
#define NR    1152
#define NC    10
#define NO    16
#define NI    8
#define CO    160          // NC * NO

// ---------------- scratch (static device allocations are the sanctioned path) ----
__device__ float g_uhat[(size_t)NB * NR * CO];   // 377 MB, [b][r][c*16+o]
__device__ float g_s[NB * CO];                   // per-iteration s accumulator
__device__ float g_V[NB * CO];                   // cumulative sum of squashed v

// ---------------- init: zero s and V ---------------------------------------------
__global__ void k_init() {
    int i = blockIdx.x * blockDim.x + threadIdx.x;
    if (i < NB * CO) { g_s[i] = 0.0f; g_V[i] = 0.0f; }
}

// ---------------- K1: u_hat[b,r,c,o] = sum_i u[b,r,i] * W[r,c,i,o] ----------------
// Block = 256 threads = 8 warps; warp w owns r = blockIdx.x*8 + w.
// Lane l owns outputs idx = l + 32k (k<5): c = idx>>4, o = idx&15.
// W coefficients (40 per lane) live in registers; loop over a b-chunk.
#define K1_NBCH 4
#define K1_BCH  (NB / K1_NBCH)   // 128

__global__ __launch_bounds__(256) void k1_uhat(const float* __restrict__ u,
                                               const float* __restrict__ W) {
    const int w = threadIdx.x >> 5;
    const int l = threadIdx.x & 31;
    const int r = blockIdx.x * 8 + w;
    const int b0 = blockIdx.y * K1_BCH;

    float Wreg[5][NI];
#pragma unroll
    for (int k = 0; k < 5; k++) {
        int idx = l + 32 * k;
        int c = idx >> 4;
        int o = idx & 15;
        const float* Wp = W + ((size_t)r * NC + c) * (NI * NO) + o;
#pragma unroll
        for (int i = 0; i < NI; i++) Wreg[k][i] = __ldg(Wp + i * NO);
    }

    const float4* u4 = reinterpret_cast<const float4*>(u);
#pragma unroll 2
    for (int b = b0; b < b0 + K1_BCH; b++) {
        size_t ub = ((size_t)b * NR + r) * 2;   // two float4 per (b,r)
        float4 ua = __ldg(&u4[ub]);
        float4 uc = __ldg(&u4[ub + 1]);
        float uu[8] = {ua.x, ua.y, ua.z, ua.w, uc.x, uc.y, uc.z, uc.w};

        float* outp = g_uhat + ((size_t)b * NR + r) * CO;
#pragma unroll
        for (int k = 0; k < 5; k++) {
            float acc = 0.0f;
#pragma unroll
            for (int i = 0; i < NI; i++) acc = fmaf(uu[i], Wreg[k][i], acc);
            outp[l + 32 * k] = acc;
        }
    }
}

// ---------------- pass: one routing iteration over u_hat --------------------------
// logits[b,r,c] = u_hat[b,r,c,:] . V[b,c,:]   (V == 0 -> exactly uniform softmax)
// p = softmax_c(logits); s[b,c,o] += p[c] * u_hat[b,r,c,o]
// Block = 256 thr = 8 warps, fixed b; warp accumulates s in regs over its r's.
#define P_BPB 2
#define P_RPB (NR / P_BPB)   // 576
#define P_RPW (P_RPB / 8)    // 72

__global__ __launch_bounds__(256) void k_pass() {
    const int w = threadIdx.x >> 5;
    const int l = threadIdx.x & 31;
    const int b = blockIdx.x;
    const int rbase = blockIdx.y * P_RPB;

    float Vreg[5];
#pragma unroll
    for (int k = 0; k < 5; k++) Vreg[k] = g_V[b * CO + l + 32 * k];

    float acc[5] = {0.f, 0.f, 0.f, 0.f, 0.f};

    for (int j = 0; j < P_RPW; j++) {
        int r = rbase + w + 8 * j;
        const float* up = g_uhat + ((size_t)b * NR + r) * CO;

        float uh[5];
#pragma unroll
        for (int k = 0; k < 5; k++) uh[k] = __ldcs(up + l + 32 * k);

        // per-class logits: reduce over the 16 lanes sharing a class
        float lg[5];
#pragma unroll
        for (int k = 0; k < 5; k++) {
            float p = uh[k] * Vreg[k];
            p += __shfl_xor_sync(0xffffffffu, p, 1);
            p += __shfl_xor_sync(0xffffffffu, p, 2);
            p += __shfl_xor_sync(0xffffffffu, p, 4);
            p += __shfl_xor_sync(0xffffffffu, p, 8);
            lg[k] = p;   // class c = 2k + (l>=16)
        }

        // softmax over 10 classes (own 5 + partner half-warp's 5)
        float m = lg[0];
#pragma unroll
        for (int k = 1; k < 5; k++) m = fmaxf(m, lg[k]);
        m = fmaxf(m, __shfl_xor_sync(0xffffffffu, m, 16));

        float e[5], ssum = 0.0f;
#pragma unroll
        for (int k = 0; k < 5; k++) { e[k] = __expf(lg[k] - m); ssum += e[k]; }
        ssum += __shfl_xor_sync(0xffffffffu, ssum, 16);
        float inv = __frcp_rn(ssum);

#pragma unroll
        for (int k = 0; k < 5; k++) acc[k] = fmaf(e[k] * inv, uh[k], acc[k]);
    }

#pragma unroll
    for (int k = 0; k < 5; k++) atomicAdd(&g_s[b * CO + l + 32 * k], acc[k]);
}

// ---------------- squash + V update (also zeroes g_s for next pass) ---------------
__global__ void k_squash(float* __restrict__ outp, int final_iter) {
    const int b = blockIdx.x;
    const int t = threadIdx.x;   // 0..159 ; c = t>>4, o = t&15 (16-groups warp-aligned)
    float s = g_s[b * CO + t];
    float sq = s * s;
    sq += __shfl_xor_sync(0xffffffffu, sq, 1);
    sq += __shfl_xor_sync(0xffffffffu, sq, 2);
    sq += __shfl_xor_sync(0xffffffffu, sq, 4);
    sq += __shfl_xor_sync(0xffffffffu, sq, 8);   // sq = |s_c|^2
    float f = sqrtf(sq) / (1.0f + sq);           // == |s| / (1+|s|^2)
    float v = f * s;
    g_s[b * CO + t] = 0.0f;                      // ready for next pass
    if (final_iter) outp[b * CO + t] = v;
    else            g_V[b * CO + t] += v;
}

// ---------------- launch -----------------------------------------------------------
extern "C" void kernel_launch(void* const* d_in, const int* in_sizes, int n_in,
                              void* d_out, int out_size) {
    const float* u = (const float*)d_in[0];   // [512,1152,8]
    const float* W = (const float*)d_in[1];   // [1,1152,10,8,16]
    float* outp = (float*)d_out;              // [512,10,16]

    k_init<<<(NB * CO + 255) / 256, 256>>>();
    k1_uhat<<<dim3(NR / 8, K1_NBCH), 256>>>(u, W);
    for (int t = 0; t < 3; t++) {
        k_pass<<<dim3(NB, P_BPB), 256>>>();
        k_squash<<<NB, CO>>>(outp, t == 2 ? 1 : 0);
    }
}

// round 2
// speedup vs baseline: 1.2930x; 1.2930x over previous
#include <cuda_runtime.h>
#include <cuda_fp16.h>
#include <cstddef>

#define NB    512
#define NR    1152
#define NC    10
#define NO    16
#define CO    160          // NC * NO
#define NB2   (NB / 2)     // b handled in pairs

// ---------------- scratch ----------------------------------------------------------
// u_hat stored fp16, b-pair packed: g_uhat2[b/2][r][c*16+o] = half2(uh[2b'], uh[2b'+1])
__device__ __half2 g_uhat2[(size_t)NB2 * NR * CO];   // 189 MB
__device__ float   g_s[NB * CO];
__device__ float   g_V[NB * CO];

// ---------------- packed f32x2 helpers ---------------------------------------------
__device__ __forceinline__ unsigned long long pk2(float x, float y) {
    unsigned long long r;
    asm("mov.b64 %0, {%1,%2};" : "=l"(r) : "f"(x), "f"(y));
    return r;
}
__device__ __forceinline__ void fma2(unsigned long long& d,
                                     unsigned long long a, unsigned long long b) {
    asm("fma.rn.f32x2 %0, %1, %2, %0;" : "+l"(d) : "l"(a), "l"(b));
}
__device__ __forceinline__ float2 upk2(unsigned long long v) {
    float2 f;
    asm("mov.b64 {%0,%1}, %2;" : "=f"(f.x), "=f"(f.y) : "l"(v));
    return f;
}

// ---------------- init: zero s and V -----------------------------------------------
__global__ void k_init() {
    int i = blockIdx.x * blockDim.x + threadIdx.x;
    if (i < NB * CO) { g_s[i] = 0.0f; g_V[i] = 0.0f; }
}

// ---------------- K1: u_hat via b-pair packed FFMA2 --------------------------------
// Warp w owns r = blockIdx.x*8+w. Lane l owns (c,o) positions l+32k, k<5.
// Processes 2 batches per iter: packed f32x2 FMA, half2 store.
#define K1_NBCH 4
#define K1_BCH  (NB / K1_NBCH)   // 128

__global__ __launch_bounds__(256) void k1_uhat(const float* __restrict__ u,
                                               const float* __restrict__ W) {
    const int w = threadIdx.x >> 5;
    const int l = threadIdx.x & 31;
    const int r = blockIdx.x * 8 + w;
    const int b0 = blockIdx.y * K1_BCH;

    unsigned long long Wp[5][8];   // W duplicated in both halves
#pragma unroll
    for (int k = 0; k < 5; k++) {
        int idx = l + 32 * k;
        int c = idx >> 4;
        int o = idx & 15;
        const float* Wq = W + ((size_t)r * NC + c) * 128 + o;
#pragma unroll
        for (int i = 0; i < 8; i++) {
            float wv = __ldg(Wq + i * 16);
            Wp[k][i] = pk2(wv, wv);
        }
    }

    const float4* u4 = reinterpret_cast<const float4*>(u);
    for (int b = b0; b < b0 + K1_BCH; b += 2) {
        float4 a0 = __ldg(&u4[((size_t)b * NR + r) * 2]);
        float4 a1 = __ldg(&u4[((size_t)b * NR + r) * 2 + 1]);
        float4 c0 = __ldg(&u4[((size_t)(b + 1) * NR + r) * 2]);
        float4 c1 = __ldg(&u4[((size_t)(b + 1) * NR + r) * 2 + 1]);

        unsigned long long up[8];
        up[0] = pk2(a0.x, c0.x); up[1] = pk2(a0.y, c0.y);
        up[2] = pk2(a0.z, c0.z); up[3] = pk2(a0.w, c0.w);
        up[4] = pk2(a1.x, c1.x); up[5] = pk2(a1.y, c1.y);
        up[6] = pk2(a1.z, c1.z); up[7] = pk2(a1.w, c1.w);

        __half2* outp = g_uhat2 + ((size_t)(b >> 1) * NR + r) * CO;
#pragma unroll
        for (int k = 0; k < 5; k++) {
            unsigned long long acc = 0ULL;   // bits 0 == {0.f, 0.f}
#pragma unroll
            for (int i = 0; i < 8; i++) fma2(acc, up[i], Wp[k][i]);
            float2 f = upk2(acc);
            outp[l + 32 * k] = __floats2half2_rn(f.x, f.y);   // lo = even b
        }
    }
}

// ---------------- pass: one routing iteration --------------------------------------
// Warp = 2 groups of 16 lanes; group g handles row r = rbase+2*pair+g.
// Lane = (g, c); active if c < 10. Lane loads u_hat[b2, r, c, 0..15] (16 half2,
// both b's of the pair) with 4x LDG.128, dots against V in-register, softmax over
// classes with 16-lane shuffles, and accumulates s locally. Block reduces in smem,
// then ~320 global atomics per block.
#define RPB     128
#define RCHUNKS (NR / RPB)   // 9

__global__ __launch_bounds__(256) void k_pass() {
    __shared__ float part[8][2 * CO];

    const int w = threadIdx.x >> 5;
    const int l = threadIdx.x & 31;
    const int b2 = blockIdx.x;
    const int rbase = blockIdx.y * RPB;
    const int g = l >> 4;
    const int c = l & 15;
    const bool act = (c < NC);

    float V0[16], V1[16];
    if (act) {
        const float4* va = reinterpret_cast<const float4*>(g_V + (2 * b2) * CO + c * 16);
        const float4* vb = reinterpret_cast<const float4*>(g_V + (2 * b2 + 1) * CO + c * 16);
#pragma unroll
        for (int q = 0; q < 4; q++) {
            float4 x = va[q];
            V0[q * 4 + 0] = x.x; V0[q * 4 + 1] = x.y; V0[q * 4 + 2] = x.z; V0[q * 4 + 3] = x.w;
            float4 y = vb[q];
            V1[q * 4 + 0] = y.x; V1[q * 4 + 1] = y.y; V1[q * 4 + 2] = y.z; V1[q * 4 + 3] = y.w;
        }
    }

    float acc0[16], acc1[16];
#pragma unroll
    for (int o = 0; o < 16; o++) { acc0[o] = 0.0f; acc1[o] = 0.0f; }

    for (int j = 0; j < RPB / 16; j++) {        // 8 r-pairs per warp
        const int r = rbase + 2 * (w * 8 + j) + g;

        float f0[16], f1[16];
        float lg0 = -1e30f, lg1 = -1e30f;
        if (act) {
            const uint4* p = reinterpret_cast<const uint4*>(
                g_uhat2 + ((size_t)b2 * NR + r) * CO + c * 16);
            union { uint4 v; __half2 h[4]; } q[4];
            q[0].v = __ldcs(p + 0); q[1].v = __ldcs(p + 1);
            q[2].v = __ldcs(p + 2); q[3].v = __ldcs(p + 3);

            float d0 = 0.0f, d1 = 0.0f;
#pragma unroll
            for (int qq = 0; qq < 4; qq++) {
#pragma unroll
                for (int m = 0; m < 4; m++) {
                    int o = qq * 4 + m;
                    float2 fv = __half22float2(q[qq].h[m]);
                    f0[o] = fv.x; f1[o] = fv.y;
                    d0 = fmaf(fv.x, V0[o], d0);
                    d1 = fmaf(fv.y, V1[o], d1);
                }
            }
            lg0 = d0; lg1 = d1;
        }

        // max over the 16-lane class group
        float m0 = lg0, m1 = lg1;
#pragma unroll
        for (int d = 1; d <= 8; d <<= 1) {
            m0 = fmaxf(m0, __shfl_xor_sync(0xffffffffu, m0, d));
            m1 = fmaxf(m1, __shfl_xor_sync(0xffffffffu, m1, d));
        }
        float e0 = act ? __expf(lg0 - m0) : 0.0f;
        float e1 = act ? __expf(lg1 - m1) : 0.0f;
        float s0 = e0, s1 = e1;
#pragma unroll
        for (int d = 1; d <= 8; d <<= 1) {
            s0 += __shfl_xor_sync(0xffffffffu, s0, d);
            s1 += __shfl_xor_sync(0xffffffffu, s1, d);
        }
        float p0 = e0 * __frcp_rn(s0);
        float p1 = e1 * __frcp_rn(s1);

        if (act) {
#pragma unroll
            for (int o = 0; o < 16; o++) {
                acc0[o] = fmaf(p0, f0[o], acc0[o]);
                acc1[o] = fmaf(p1, f1[o], acc1[o]);
            }
        }
    }

    // combine the two r-groups (same c, same b-pair)
#pragma unroll
    for (int o = 0; o < 16; o++) {
        acc0[o] += __shfl_xor_sync(0xffffffffu, acc0[o], 16);
        acc1[o] += __shfl_xor_sync(0xffffffffu, acc1[o], 16);
    }
    if (g == 0 && act) {
#pragma unroll
        for (int o = 0; o < 16; o++) {
            part[w][c * 16 + o]      = acc0[o];
            part[w][CO + c * 16 + o] = acc1[o];
        }
    }
    __syncthreads();

    for (int t = threadIdx.x; t < 2 * CO; t += 256) {
        float s = 0.0f;
#pragma unroll
        for (int ww = 0; ww < 8; ww++) s += part[ww][t];
        int bb = (t >= CO);
        atomicAdd(&g_s[(2 * b2 + bb) * CO + (t - bb * CO)], s);
    }
}

// ---------------- squash + V update (also zeroes g_s) ------------------------------
__global__ void k_squash(float* __restrict__ outp, int final_iter) {
    const int b = blockIdx.x;
    const int t = threadIdx.x;   // 0..159
    float s = g_s[b * CO + t];
    float sq = s * s;
    sq += __shfl_xor_sync(0xffffffffu, sq, 1);
    sq += __shfl_xor_sync(0xffffffffu, sq, 2);
    sq += __shfl_xor_sync(0xffffffffu, sq, 4);
    sq += __shfl_xor_sync(0xffffffffu, sq, 8);   // |s_c|^2
    float f = sqrtf(sq) / (1.0f + sq);           // |s| / (1+|s|^2)
    float v = f * s;
    g_s[b * CO + t] = 0.0f;
    if (final_iter) outp[b * CO + t] = v;
    else            g_V[b * CO + t] += v;
}

// ---------------- launch ------------------------------------------------------------
extern "C" void kernel_launch(void* const* d_in, const int* in_sizes, int n_in,
                              void* d_out, int out_size) {
    const float* u = (const float*)d_in[0];   // [512,1152,8]
    const float* W = (const float*)d_in[1];   // [1,1152,10,8,16]
    float* outp = (float*)d_out;              // [512,10,16]

    k_init<<<(NB * CO + 255) / 256, 256>>>();
    k1_uhat<<<dim3(NR / 8, K1_NBCH), 256>>>(u, W);
    for (int t = 0; t < 3; t++) {
        k_pass<<<dim3(NB2, RCHUNKS), 256>>>();
        k_squash<<<NB, CO>>>(outp, t == 2 ? 1 : 0);
    }
}